// round 6
// baseline (speedup 1.0000x reference)
#include <cuda_runtime.h>
#include <cuda_bf16.h>
#include <cstdint>

#define BATCH 2
#define SEQ 2048
#define NEMBD 1024
#define NHEAD 16
#define HDIM 64
#define WINDOW 256
#define ATT_SCALE 0.125f   // 1/sqrt(64)

typedef unsigned long long ull;

// ---------------- device scratch (allocation-free rule) ----------------
__device__ float g_qkv[(size_t)BATCH * SEQ * 3 * NEMBD];       // [4096, 3072] fp32
__device__ __nv_bfloat16 g_ah[(size_t)4096 * 1024];            // hidden hi
__device__ __nv_bfloat16 g_al[(size_t)4096 * 1024];            // hidden lo
__device__ __nv_bfloat16 g_wh[(size_t)3072 * 1024];            // w_attn^T hi [N][K]
__device__ __nv_bfloat16 g_wl[(size_t)3072 * 1024];
__device__ __nv_bfloat16 g_ph[(size_t)1024 * 1024];            // w_proj^T hi
__device__ __nv_bfloat16 g_pl[(size_t)1024 * 1024];
__device__ __nv_bfloat16 g_oh[(size_t)4096 * 1024];            // attn out hi
__device__ __nv_bfloat16 g_ol[(size_t)4096 * 1024];

// ---------------- small helpers ----------------
__device__ __forceinline__ uint32_t smem_u32(const void* p) {
    uint32_t a;
    asm("{ .reg .u64 t; cvta.to.shared.u64 t, %1; cvt.u32.u64 %0, t; }"
        : "=r"(a) : "l"(p));
    return a;
}

__device__ __forceinline__ void split4(float4 v, uint2& hi, uint2& lo) {
    __nv_bfloat162 h01 = __floats2bfloat162_rn(v.x, v.y);
    __nv_bfloat162 h23 = __floats2bfloat162_rn(v.z, v.w);
    float l0 = v.x - __low2float(h01), l1 = v.y - __high2float(h01);
    float l2 = v.z - __low2float(h23), l3 = v.w - __high2float(h23);
    __nv_bfloat162 lo01 = __floats2bfloat162_rn(l0, l1);
    __nv_bfloat162 lo23 = __floats2bfloat162_rn(l2, l3);
    hi.x = *(uint32_t*)&h01; hi.y = *(uint32_t*)&h23;
    lo.x = *(uint32_t*)&lo01; lo.y = *(uint32_t*)&lo23;
}

__device__ __forceinline__ void mma16816(float* c, const uint32_t* a, const uint32_t* b) {
    asm volatile(
        "mma.sync.aligned.m16n8k16.row.col.f32.bf16.bf16.f32 "
        "{%0,%1,%2,%3},{%4,%5,%6,%7},{%8,%9},{%0,%1,%2,%3};"
        : "+f"(c[0]), "+f"(c[1]), "+f"(c[2]), "+f"(c[3])
        : "r"(a[0]), "r"(a[1]), "r"(a[2]), "r"(a[3]), "r"(b[0]), "r"(b[1]));
}
__device__ __forceinline__ void ldsm4(uint32_t* r, uint32_t addr) {
    asm volatile("ldmatrix.sync.aligned.m8n8.x4.shared.b16 {%0,%1,%2,%3}, [%4];"
                 : "=r"(r[0]), "=r"(r[1]), "=r"(r[2]), "=r"(r[3]) : "r"(addr));
}
__device__ __forceinline__ void cpa16(uint32_t saddr, const void* gaddr) {
    asm volatile("cp.async.cg.shared.global [%0], [%1], 16;" :: "r"(saddr), "l"(gaddr));
}
#define CP_COMMIT() asm volatile("cp.async.commit_group;")
#define CP_WAIT2()  asm volatile("cp.async.wait_group 2;")

// packed f32x2 ops
__device__ __forceinline__ ull pk2(float a, float b) {
    ull r; asm("mov.b64 %0, {%1,%2};" : "=l"(r) : "f"(a), "f"(b)); return r;
}
__device__ __forceinline__ void upk2(ull v, float& a, float& b) {
    asm("mov.b64 {%0,%1}, %2;" : "=f"(a), "=f"(b) : "l"(v));
}
__device__ __forceinline__ void fma2(ull& d, ull a, ull b) {
    asm("fma.rn.f32x2 %0, %1, %2, %0;" : "+l"(d) : "l"(a), "l"(b));
}
__device__ __forceinline__ void mul2(ull& d, ull a) {
    asm("fma.rn.f32x2 %0, %0, %1, %2;" : "+l"(d) : "l"(a), "l"(0ULL));
}

// 64B-row swizzle: byte = row*64 + (col16 ^ (((row>>1)&3)<<4))
// Conflict-free for 16B cp.async writes and ldmatrix 8-row phases.
__device__ __forceinline__ uint32_t swz32(int row, int col) {
    return (uint32_t)(row * 64 + (col ^ (((row >> 1) & 3) << 4)));
}

// ===========================================================================
// conversion kernels
// ===========================================================================
__global__ void split_kernel(const float* __restrict__ src,
                             __nv_bfloat16* __restrict__ hi,
                             __nv_bfloat16* __restrict__ lo, int n4) {
    int i = blockIdx.x * blockDim.x + threadIdx.x;
    if (i < n4) {
        float4 v = *(const float4*)(src + (size_t)i * 4);
        uint2 h, l; split4(v, h, l);
        *(uint2*)(hi + (size_t)i * 4) = h;
        *(uint2*)(lo + (size_t)i * 4) = l;
    }
}

// src [K,N] fp32 row-major -> dst [N][K] bf16 hi/lo
__global__ void split_tr_kernel(const float* __restrict__ src,
                                __nv_bfloat16* __restrict__ hi,
                                __nv_bfloat16* __restrict__ lo, int K, int N) {
    __shared__ float t[32][33];
    const int n0 = blockIdx.x * 32, k0 = blockIdx.y * 32;
    const int tx = threadIdx.x, ty = threadIdx.y;   // 32 x 8
#pragma unroll
    for (int i = 0; i < 4; i++)
        t[ty + i * 8][tx] = src[(size_t)(k0 + ty + i * 8) * N + n0 + tx];
    __syncthreads();
#pragma unroll
    for (int i = 0; i < 4; i++) {
        int n = ty + i * 8;
        float v = t[tx][n];
        __nv_bfloat16 h = __float2bfloat16(v);
        float l = v - __bfloat162float(h);
        hi[(size_t)(n0 + n) * K + k0 + tx] = h;
        lo[(size_t)(n0 + n) * K + k0 + tx] = __float2bfloat16(l);
    }
}

// ===========================================================================
// split-precision bf16 GEMM: C[M,N] = Ahl[M,K] @ Bhl[N,K]^T + bias
// CTA 128x128, BK=32, 3-stage cp.async pipeline, 96KB smem -> 2 CTAs/SM.
// ===========================================================================
#define BUF   8192                          // 128 rows x 64B
#define ST_AH 0
#define ST_AL 8192
#define ST_BH 16384
#define ST_BL 24576
#define ST_SZ 32768
#define GSMEM (3 * ST_SZ)                   // 98304

__global__ __launch_bounds__(256, 2)
void gemm_bf16_kernel(const __nv_bfloat16* __restrict__ Ah, const __nv_bfloat16* __restrict__ Al,
                      const __nv_bfloat16* __restrict__ Bh, const __nv_bfloat16* __restrict__ Bl,
                      const float* __restrict__ bias, float* __restrict__ C,
                      int M, int N, int K) {
    extern __shared__ char sm[];
    const uint32_t sb = smem_u32(sm);
    const int tid = threadIdx.x, lane = tid & 31, wid = tid >> 5;
    const int m0 = blockIdx.y * 128, n0 = blockIdx.x * 128;
    const int wm = wid >> 2, wn = wid & 3;          // 2 x 4 warp grid, warp tile 64x32
    const int l15 = lane & 15, chi = (lane >> 4) * 16;
    const int NT = K / 32;

    float acc[4][4][4];
#pragma unroll
    for (int i = 0; i < 4; i++)
#pragma unroll
        for (int j = 0; j < 4; j++)
#pragma unroll
            for (int r = 0; r < 4; r++) acc[i][j][r] = 0.f;

    // cp.async: 512 16B-tasks per buffer, 2 per thread. task -> (row, chunk)
    const int t_r0 = (tid * 2) >> 2,   t_c0 = (tid * 2) & 3;
    const int t_r1 = (tid * 2 + 1) >> 2, t_c1 = (tid * 2 + 1) & 3;

    auto load_stage = [&](int s, int kt) {
        const uint32_t sbase = sb + s * ST_SZ;
        const size_t gk0 = (size_t)kt * 32 + t_c0 * 8;
        const size_t gk1 = (size_t)kt * 32 + t_c1 * 8;
        const uint32_t so0 = swz32(t_r0, t_c0 * 16);
        const uint32_t so1 = swz32(t_r1, t_c1 * 16);
        cpa16(sbase + ST_AH + so0, Ah + (size_t)(m0 + t_r0) * K + gk0);
        cpa16(sbase + ST_AH + so1, Ah + (size_t)(m0 + t_r1) * K + gk1);
        cpa16(sbase + ST_AL + so0, Al + (size_t)(m0 + t_r0) * K + gk0);
        cpa16(sbase + ST_AL + so1, Al + (size_t)(m0 + t_r1) * K + gk1);
        cpa16(sbase + ST_BH + so0, Bh + (size_t)(n0 + t_r0) * K + gk0);
        cpa16(sbase + ST_BH + so1, Bh + (size_t)(n0 + t_r1) * K + gk1);
        cpa16(sbase + ST_BL + so0, Bl + (size_t)(n0 + t_r0) * K + gk0);
        cpa16(sbase + ST_BL + so1, Bl + (size_t)(n0 + t_r1) * K + gk1);
    };

    load_stage(0, 0); CP_COMMIT();
    load_stage(1, 1); CP_COMMIT();
    load_stage(2, 2); CP_COMMIT();

    int s = 0;
    for (int t = 0; t < NT; t++) {
        CP_WAIT2();
        __syncthreads();

        const uint32_t abase = sb + s * ST_SZ;
#pragma unroll
        for (int ks = 0; ks < 2; ks++) {
            const int cb = ks * 32 + chi;
            uint32_t Af[4][4], Bf[2][4], Lf[4][4], Mf[2][4];
#pragma unroll
            for (int mt = 0; mt < 4; mt++)
                ldsm4(Af[mt], abase + ST_AH + swz32(wm * 64 + mt * 16 + l15, cb));
#pragma unroll
            for (int bt = 0; bt < 2; bt++)
                ldsm4(Bf[bt], abase + ST_BH + swz32(wn * 32 + bt * 16 + l15, cb));
            // pass 1: Ah * Bh
#pragma unroll
            for (int mt = 0; mt < 4; mt++)
#pragma unroll
                for (int nt = 0; nt < 4; nt++) {
                    uint32_t b[2] = { Bf[nt >> 1][nt & 1], Bf[nt >> 1][(nt & 1) + 2] };
                    mma16816(acc[mt][nt], Af[mt], b);
                }
            // pass 2: Ah * Bl
#pragma unroll
            for (int bt = 0; bt < 2; bt++)
                ldsm4(Mf[bt], abase + ST_BL + swz32(wn * 32 + bt * 16 + l15, cb));
#pragma unroll
            for (int mt = 0; mt < 4; mt++)
#pragma unroll
                for (int nt = 0; nt < 4; nt++) {
                    uint32_t b[2] = { Mf[nt >> 1][nt & 1], Mf[nt >> 1][(nt & 1) + 2] };
                    mma16816(acc[mt][nt], Af[mt], b);
                }
            // pass 3: Al * Bh
#pragma unroll
            for (int mt = 0; mt < 4; mt++)
                ldsm4(Lf[mt], abase + ST_AL + swz32(wm * 64 + mt * 16 + l15, cb));
#pragma unroll
            for (int mt = 0; mt < 4; mt++)
#pragma unroll
                for (int nt = 0; nt < 4; nt++) {
                    uint32_t b[2] = { Bf[nt >> 1][nt & 1], Bf[nt >> 1][(nt & 1) + 2] };
                    mma16816(acc[mt][nt], Lf[mt], b);
                }
        }
        __syncthreads();
        if (t + 3 < NT) { load_stage(s, t + 3); CP_COMMIT(); }
        s = (s == 2) ? 0 : s + 1;
    }

    // epilogue
    const int g = lane >> 2, tig = lane & 3;
#pragma unroll
    for (int mt = 0; mt < 4; mt++) {
#pragma unroll
        for (int nt = 0; nt < 4; nt++) {
            int row0 = m0 + wm * 64 + mt * 16 + g;
            int col  = n0 + wn * 32 + nt * 8 + tig * 2;
            float2 bb = *(const float2*)(bias + col);
            float2 v0 = make_float2(acc[mt][nt][0] + bb.x, acc[mt][nt][1] + bb.y);
            float2 v1 = make_float2(acc[mt][nt][2] + bb.x, acc[mt][nt][3] + bb.y);
            *(float2*)(C + (size_t)row0 * N + col)       = v0;
            *(float2*)(C + (size_t)(row0 + 8) * N + col) = v1;
        }
    }
}

// ===========================================================================
// Sliding-window causal attention, packed f32x2 math.
// Writes split bf16 (hi/lo) directly for the proj GEMM.
// ===========================================================================
__global__ __launch_bounds__(64)
void attn_kernel(const float* __restrict__ qkv,
                 __nv_bfloat16* __restrict__ oh, __nv_bfloat16* __restrict__ ol) {
    const int b  = blockIdx.z;
    const int h  = blockIdx.y;
    const int qs = blockIdx.x * 64;
    const int tid = threadIdx.x;
    const int i = qs + tid;

    __shared__ ull ks2[64][32];
    __shared__ ull vs2[64][32];

    const size_t rowStride = 3 * NEMBD;

    const float* qptr = qkv + ((size_t)b * SEQ + i) * rowStride + h * HDIM;
    ull q2[32];
#pragma unroll
    for (int d4 = 0; d4 < 16; d4++)
        *(float4*)&q2[d4 * 2] = *(const float4*)(qptr + d4 * 4);

    ull acc2[32];
#pragma unroll
    for (int d = 0; d < 32; d++) acc2[d] = 0ULL;
    float m = -1e30f, l = 0.f;

    int kt0 = qs - WINDOW;
    if (kt0 < 0) kt0 = 0;

    for (int kt = kt0; kt <= qs; kt += 64) {
        const float* kbase = qkv + ((size_t)b * SEQ + kt) * rowStride + NEMBD + h * HDIM;
        const float* vbase = kbase + NEMBD;
        float* ksf = (float*)&ks2[0][0];
        float* vsf = (float*)&vs2[0][0];
#pragma unroll
        for (int t = 0; t < 16; t++) {
            int idx4 = tid + t * 64;
            int r = idx4 >> 4;
            int c = (idx4 & 15) << 2;
            *(float4*)(ksf + r * 64 + c) = *(const float4*)(kbase + (size_t)r * rowStride + c);
            *(float4*)(vsf + r * 64 + c) = *(const float4*)(vbase + (size_t)r * rowStride + c);
        }
        __syncthreads();

        for (int j = 0; j < 64; j++) {
            const int jg = kt + j;
            ull s2a = 0ULL, s2b = 0ULL, s2c = 0ULL, s2d = 0ULL;
#pragma unroll
            for (int d = 0; d < 32; d += 4) {
                fma2(s2a, q2[d + 0], ks2[j][d + 0]);
                fma2(s2b, q2[d + 1], ks2[j][d + 1]);
                fma2(s2c, q2[d + 2], ks2[j][d + 2]);
                fma2(s2d, q2[d + 3], ks2[j][d + 3]);
            }
            float xa, xb, xc, xd, ya, yb, yc, yd;
            upk2(s2a, xa, ya); upk2(s2b, xb, yb); upk2(s2c, xc, yc); upk2(s2d, xd, yd);
            float s = ((xa + xb) + (xc + xd)) + ((ya + yb) + (yc + yd));
            s *= ATT_SCALE;
            s = fminf(fmaxf(s, -10000.f), 10000.f);
            const bool valid = (jg <= i) && (jg > i - WINDOW);
            if (valid) {
                if (s > m) {
                    const float corr = __expf(m - s);
                    const ull corr2 = pk2(corr, corr);
                    l *= corr;
#pragma unroll
                    for (int d = 0; d < 32; d++) mul2(acc2[d], corr2);
                    m = s;
                }
                const float p = __expf(s - m);
                l += p;
                const ull p2 = pk2(p, p);
#pragma unroll
                for (int d = 0; d < 32; d++) fma2(acc2[d], p2, vs2[j][d]);
            }
        }
        __syncthreads();
    }

    const float inv = 1.f / l;
    const size_t obase = ((size_t)b * SEQ + i) * NEMBD + h * HDIM;
#pragma unroll
    for (int d = 0; d < 32; d += 2) {
        float a0, a1, a2, a3;
        upk2(acc2[d], a0, a1); upk2(acc2[d + 1], a2, a3);
        float4 o = make_float4(a0 * inv, a1 * inv, a2 * inv, a3 * inv);
        uint2 hv, lv;
        split4(o, hv, lv);
        *(uint2*)(oh + obase + d * 2) = hv;
        *(uint2*)(ol + obase + d * 2) = lv;
    }
}

// ---------------------------------------------------------------------------
extern "C" void kernel_launch(void* const* d_in, const int* in_sizes, int n_in,
                              void* d_out, int out_size) {
    const float* hidden = (const float*)d_in[0];  // [B, T, E]
    const float* w_attn = (const float*)d_in[1];  // [E, 3E]
    const float* b_attn = (const float*)d_in[2];  // [3E]
    const float* w_proj = (const float*)d_in[3];  // [E, E]
    const float* b_proj = (const float*)d_in[4];  // [E]
    float* out = (float*)d_out;

    float* qkv; cudaGetSymbolAddress((void**)&qkv, g_qkv);
    __nv_bfloat16 *ah, *al, *wh, *wl, *ph, *pl, *oh, *ol;
    cudaGetSymbolAddress((void**)&ah, g_ah); cudaGetSymbolAddress((void**)&al, g_al);
    cudaGetSymbolAddress((void**)&wh, g_wh); cudaGetSymbolAddress((void**)&wl, g_wl);
    cudaGetSymbolAddress((void**)&ph, g_ph); cudaGetSymbolAddress((void**)&pl, g_pl);
    cudaGetSymbolAddress((void**)&oh, g_oh); cudaGetSymbolAddress((void**)&ol, g_ol);

    const int M = BATCH * SEQ;       // 4096
    const int E = NEMBD;             // 1024

    cudaFuncSetAttribute(gemm_bf16_kernel,
                         cudaFuncAttributeMaxDynamicSharedMemorySize, GSMEM);

    // 0a) split hidden -> bf16 hi/lo
    {
        int n4 = M * E / 4;
        split_kernel<<<(n4 + 255) / 256, 256>>>(hidden, ah, al, n4);
    }
    // 0b) split+transpose weights
    split_tr_kernel<<<dim3(3 * E / 32, E / 32), dim3(32, 8)>>>(w_attn, wh, wl, E, 3 * E);
    split_tr_kernel<<<dim3(E / 32, E / 32), dim3(32, 8)>>>(w_proj, ph, pl, E, E);

    // 1) QKV projection
    gemm_bf16_kernel<<<dim3(3 * E / 128, M / 128), 256, GSMEM>>>(
        ah, al, wh, wl, b_attn, qkv, M, 3 * E, E);
    // 2) windowed attention (writes split bf16)
    attn_kernel<<<dim3(SEQ / 64, NHEAD, BATCH), 64>>>(qkv, oh, ol);
    // 3) output projection
    gemm_bf16_kernel<<<dim3(E / 128, M / 128), 256, GSMEM>>>(
        oh, ol, ph, pl, b_proj, out, M, E, E);
}

// round 7
// speedup vs baseline: 1.5132x; 1.5132x over previous
#include <cuda_runtime.h>
#include <cuda_bf16.h>
#include <cstdint>

#define BATCH 2
#define SEQ 2048
#define NEMBD 1024
#define NHEAD 16
#define HDIM 64
#define WINDOW 256
#define ATT_SCALE 0.125f   // 1/sqrt(64)

// ---------------- device scratch (allocation-free rule) ----------------
__device__ __nv_bfloat16 g_kvh[(size_t)4096 * 3072];           // qkv hi
__device__ __nv_bfloat16 g_kvl[(size_t)4096 * 3072];           // qkv lo
__device__ __nv_bfloat16 g_ah[(size_t)4096 * 1024];            // hidden hi
__device__ __nv_bfloat16 g_al[(size_t)4096 * 1024];            // hidden lo
__device__ __nv_bfloat16 g_wh[(size_t)3072 * 1024];            // w_attn^T hi [N][K]
__device__ __nv_bfloat16 g_wl[(size_t)3072 * 1024];
__device__ __nv_bfloat16 g_ph[(size_t)1024 * 1024];            // w_proj^T hi
__device__ __nv_bfloat16 g_pl[(size_t)1024 * 1024];
__device__ __nv_bfloat16 g_oh[(size_t)4096 * 1024];            // attn out hi
__device__ __nv_bfloat16 g_ol[(size_t)4096 * 1024];

// ---------------- helpers ----------------
__device__ __forceinline__ uint32_t smem_u32(const void* p) {
    uint32_t a;
    asm("{ .reg .u64 t; cvta.to.shared.u64 t, %1; cvt.u32.u64 %0, t; }"
        : "=r"(a) : "l"(p));
    return a;
}
__device__ __forceinline__ void split4(float4 v, uint2& hi, uint2& lo) {
    __nv_bfloat162 h01 = __floats2bfloat162_rn(v.x, v.y);
    __nv_bfloat162 h23 = __floats2bfloat162_rn(v.z, v.w);
    float l0 = v.x - __low2float(h01), l1 = v.y - __high2float(h01);
    float l2 = v.z - __low2float(h23), l3 = v.w - __high2float(h23);
    __nv_bfloat162 lo01 = __floats2bfloat162_rn(l0, l1);
    __nv_bfloat162 lo23 = __floats2bfloat162_rn(l2, l3);
    hi.x = *(uint32_t*)&h01; hi.y = *(uint32_t*)&h23;
    lo.x = *(uint32_t*)&lo01; lo.y = *(uint32_t*)&lo23;
}
__device__ __forceinline__ void split2(float a, float b, uint32_t& hi, uint32_t& lo) {
    __nv_bfloat162 h = __floats2bfloat162_rn(a, b);
    float ra = a - __low2float(h), rb = b - __high2float(h);
    __nv_bfloat162 L = __floats2bfloat162_rn(ra, rb);
    hi = *(uint32_t*)&h; lo = *(uint32_t*)&L;
}
__device__ __forceinline__ void mma16816(float* c, const uint32_t* a, const uint32_t* b) {
    asm volatile(
        "mma.sync.aligned.m16n8k16.row.col.f32.bf16.bf16.f32 "
        "{%0,%1,%2,%3},{%4,%5,%6,%7},{%8,%9},{%0,%1,%2,%3};"
        : "+f"(c[0]), "+f"(c[1]), "+f"(c[2]), "+f"(c[3])
        : "r"(a[0]), "r"(a[1]), "r"(a[2]), "r"(a[3]), "r"(b[0]), "r"(b[1]));
}
__device__ __forceinline__ void ldsm4(uint32_t* r, uint32_t addr) {
    asm volatile("ldmatrix.sync.aligned.m8n8.x4.shared.b16 {%0,%1,%2,%3}, [%4];"
                 : "=r"(r[0]), "=r"(r[1]), "=r"(r[2]), "=r"(r[3]) : "r"(addr));
}
__device__ __forceinline__ void ldsm4t(uint32_t* r, uint32_t addr) {
    asm volatile("ldmatrix.sync.aligned.m8n8.x4.trans.shared.b16 {%0,%1,%2,%3}, [%4];"
                 : "=r"(r[0]), "=r"(r[1]), "=r"(r[2]), "=r"(r[3]) : "r"(addr));
}
__device__ __forceinline__ void cpa16(uint32_t saddr, const void* gaddr) {
    asm volatile("cp.async.cg.shared.global [%0], [%1], 16;" :: "r"(saddr), "l"(gaddr));
}
#define CP_COMMIT() asm volatile("cp.async.commit_group;")
#define CP_WAIT1()  asm volatile("cp.async.wait_group 1;")

// SW128 swizzle for 128B rows
__device__ __forceinline__ uint32_t swz(int row, int col) {
    return (uint32_t)(row * 128 + (col ^ ((row & 7) << 4)));
}
__device__ __forceinline__ float qmax(float v) {
    v = fmaxf(v, __shfl_xor_sync(0xFFFFFFFFu, v, 1));
    v = fmaxf(v, __shfl_xor_sync(0xFFFFFFFFu, v, 2));
    return v;
}
__device__ __forceinline__ float qsum(float v) {
    v += __shfl_xor_sync(0xFFFFFFFFu, v, 1);
    v += __shfl_xor_sync(0xFFFFFFFFu, v, 2);
    return v;
}

// ===========================================================================
// conversion kernels
// ===========================================================================
__global__ void split_kernel(const float* __restrict__ src,
                             __nv_bfloat16* __restrict__ hi,
                             __nv_bfloat16* __restrict__ lo, int n4) {
    int i = blockIdx.x * blockDim.x + threadIdx.x;
    if (i < n4) {
        float4 v = *(const float4*)(src + (size_t)i * 4);
        uint2 h, l; split4(v, h, l);
        *(uint2*)(hi + (size_t)i * 4) = h;
        *(uint2*)(lo + (size_t)i * 4) = l;
    }
}
__global__ void split_tr_kernel(const float* __restrict__ src,
                                __nv_bfloat16* __restrict__ hi,
                                __nv_bfloat16* __restrict__ lo, int K, int N) {
    __shared__ float t[32][33];
    const int n0 = blockIdx.x * 32, k0 = blockIdx.y * 32;
    const int tx = threadIdx.x, ty = threadIdx.y;   // 32 x 8
#pragma unroll
    for (int i = 0; i < 4; i++)
        t[ty + i * 8][tx] = src[(size_t)(k0 + ty + i * 8) * N + n0 + tx];
    __syncthreads();
#pragma unroll
    for (int i = 0; i < 4; i++) {
        int n = ty + i * 8;
        float v = t[tx][n];
        __nv_bfloat16 h = __float2bfloat16(v);
        float l = v - __bfloat162float(h);
        hi[(size_t)(n0 + n) * K + k0 + tx] = h;
        lo[(size_t)(n0 + n) * K + k0 + tx] = __float2bfloat16(l);
    }
}

// ===========================================================================
// split-precision bf16 GEMM (R5 config): C = A@B^T + bias
// CTA 128x128, BK=64, 2-stage cp.async, SW128, ldmatrix.
// If Ch != null, writes split bf16 hi/lo instead of fp32 C.
// ===========================================================================
#define ST_AH 0
#define ST_AL 16384
#define ST_BH 32768
#define ST_BL 49152
#define ST_SZ 65536
#define GSMEM (2 * ST_SZ)

__global__ __launch_bounds__(256, 1)
void gemm_bf16_kernel(const __nv_bfloat16* __restrict__ Ah, const __nv_bfloat16* __restrict__ Al,
                      const __nv_bfloat16* __restrict__ Bh, const __nv_bfloat16* __restrict__ Bl,
                      const float* __restrict__ bias, float* __restrict__ C,
                      __nv_bfloat16* __restrict__ Ch, __nv_bfloat16* __restrict__ Cl,
                      int M, int N, int K) {
    extern __shared__ char sm[];
    const uint32_t sb = smem_u32(sm);
    const int tid = threadIdx.x, lane = tid & 31, wid = tid >> 5;
    const int m0 = blockIdx.y * 128, n0 = blockIdx.x * 128;
    const int wm = wid >> 2, wn = wid & 3;
    const int l15 = lane & 15, chi = (lane >> 4) * 16;
    const int lrow = tid >> 3, lc = tid & 7;
    const int NT = K / 64;

    float acc[4][4][4];
#pragma unroll
    for (int i = 0; i < 4; i++)
#pragma unroll
        for (int j = 0; j < 4; j++)
#pragma unroll
            for (int r = 0; r < 4; r++) acc[i][j][r] = 0.f;

    auto load_stage = [&](int s, int kt) {
        const uint32_t sbase = sb + s * ST_SZ;
        const size_t gk = (size_t)kt * 64 + lc * 8;
#pragma unroll
        for (int i = 0; i < 4; i++) {
            const int row = lrow + i * 32;
            const uint32_t so = swz(row, lc * 16);
            cpa16(sbase + ST_AH + so, Ah + (size_t)(m0 + row) * K + gk);
            cpa16(sbase + ST_AL + so, Al + (size_t)(m0 + row) * K + gk);
            cpa16(sbase + ST_BH + so, Bh + (size_t)(n0 + row) * K + gk);
            cpa16(sbase + ST_BL + so, Bl + (size_t)(n0 + row) * K + gk);
        }
    };

    load_stage(0, 0); CP_COMMIT();
    load_stage(1, 1); CP_COMMIT();

    for (int t = 0; t < NT; t++) {
        const int s = t & 1;
        CP_WAIT1();
        __syncthreads();

        const uint32_t abase = sb + s * ST_SZ;
#pragma unroll
        for (int ks = 0; ks < 4; ks++) {
            const int cb = ks * 32 + chi;
            uint32_t Af[4][4], Bf[2][4], Lf[4][4], Mf[2][4];
#pragma unroll
            for (int mt = 0; mt < 4; mt++)
                ldsm4(Af[mt], abase + ST_AH + swz(wm * 64 + mt * 16 + l15, cb));
#pragma unroll
            for (int bt = 0; bt < 2; bt++)
                ldsm4(Bf[bt], abase + ST_BH + swz(wn * 32 + bt * 16 + l15, cb));
#pragma unroll
            for (int mt = 0; mt < 4; mt++)
#pragma unroll
                for (int nt = 0; nt < 4; nt++) {
                    uint32_t b[2] = { Bf[nt >> 1][nt & 1], Bf[nt >> 1][(nt & 1) + 2] };
                    mma16816(acc[mt][nt], Af[mt], b);
                }
#pragma unroll
            for (int bt = 0; bt < 2; bt++)
                ldsm4(Mf[bt], abase + ST_BL + swz(wn * 32 + bt * 16 + l15, cb));
#pragma unroll
            for (int mt = 0; mt < 4; mt++)
#pragma unroll
                for (int nt = 0; nt < 4; nt++) {
                    uint32_t b[2] = { Mf[nt >> 1][nt & 1], Mf[nt >> 1][(nt & 1) + 2] };
                    mma16816(acc[mt][nt], Af[mt], b);
                }
#pragma unroll
            for (int mt = 0; mt < 4; mt++)
                ldsm4(Lf[mt], abase + ST_AL + swz(wm * 64 + mt * 16 + l15, cb));
#pragma unroll
            for (int mt = 0; mt < 4; mt++)
#pragma unroll
                for (int nt = 0; nt < 4; nt++) {
                    uint32_t b[2] = { Bf[nt >> 1][nt & 1], Bf[nt >> 1][(nt & 1) + 2] };
                    mma16816(acc[mt][nt], Lf[mt], b);
                }
        }
        __syncthreads();
        if (t + 2 < NT) { load_stage(s, t + 2); CP_COMMIT(); }
    }

    const int g = lane >> 2, tig = lane & 3;
#pragma unroll
    for (int mt = 0; mt < 4; mt++) {
#pragma unroll
        for (int nt = 0; nt < 4; nt++) {
            int row0 = m0 + wm * 64 + mt * 16 + g;
            int col  = n0 + wn * 32 + nt * 8 + tig * 2;
            float2 bb = *(const float2*)(bias + col);
            float x0 = acc[mt][nt][0] + bb.x, x1 = acc[mt][nt][1] + bb.y;
            float x2 = acc[mt][nt][2] + bb.x, x3 = acc[mt][nt][3] + bb.y;
            if (Ch) {
                uint32_t h, l;
                split2(x0, x1, h, l);
                *(uint32_t*)(Ch + (size_t)row0 * N + col) = h;
                *(uint32_t*)(Cl + (size_t)row0 * N + col) = l;
                split2(x2, x3, h, l);
                *(uint32_t*)(Ch + (size_t)(row0 + 8) * N + col) = h;
                *(uint32_t*)(Cl + (size_t)(row0 + 8) * N + col) = l;
            } else {
                *(float2*)(C + (size_t)row0 * N + col)       = make_float2(x0, x1);
                *(float2*)(C + (size_t)(row0 + 8) * N + col) = make_float2(x2, x3);
            }
        }
    }
}

// ===========================================================================
// Flash attention via mma.sync with split-bf16 precision.
// 1 CTA = 64 queries of one (b,h); 4 warps x 16 rows; 128 threads.
// qkv stored as split bf16 [token][3072] (q|k|v), stride 3072.
// ===========================================================================
#define A_KH 0
#define A_KL 8192
#define A_VH 16384
#define A_VL 24576
#define A_SMEM 32768

__global__ __launch_bounds__(128)
void attn_mma_kernel(const __nv_bfloat16* __restrict__ qh,
                     const __nv_bfloat16* __restrict__ ql,
                     __nv_bfloat16* __restrict__ oh, __nv_bfloat16* __restrict__ ol) {
    extern __shared__ char sm[];
    const uint32_t sb = smem_u32(sm);
    const int b = blockIdx.z, h = blockIdx.y, qs = blockIdx.x * 64;
    const int tid = threadIdx.x, lane = tid & 31, wid = tid >> 5;
    const int l15 = lane & 15, chi = (lane >> 4) * 16;
    const int g = lane >> 2, tig = lane & 3;
    const size_t RS = 3 * NEMBD;                   // qkv row stride
    const int hcol = h * HDIM;

    // ---- stage Q through KH/KL, extract fragments ----
    {
#pragma unroll
        for (int i = 0; i < 8; i++) {
            int idx = tid + i * 128;               // 0..1023
            int buf = idx >> 9;                    // 0: hi, 1: lo
            int rem = idx & 511;
            int r = rem >> 3, c = rem & 7;
            const __nv_bfloat16* src = (buf == 0 ? qh : ql)
                + ((size_t)(b * SEQ + qs + r)) * RS + hcol + c * 8;
            *(uint4*)(sm + (buf == 0 ? A_KH : A_KL) + swz(r, c * 16)) = *(const uint4*)src;
        }
    }
    __syncthreads();
    uint32_t Qfh[4][4], Qfl[4][4];
#pragma unroll
    for (int kk = 0; kk < 4; kk++) {
        ldsm4(Qfh[kk], sb + A_KH + swz(wid * 16 + l15, kk * 32 + chi));
        ldsm4(Qfl[kk], sb + A_KL + swz(wid * 16 + l15, kk * 32 + chi));
    }
    __syncthreads();

    float o[8][4];
#pragma unroll
    for (int i = 0; i < 8; i++)
#pragma unroll
        for (int r = 0; r < 4; r++) o[i][r] = 0.f;
    float m0 = -1e30f, m1 = -1e30f, l0 = 0.f, l1 = 0.f;
    const int row0 = qs + wid * 16 + g, row1 = row0 + 8;

    int kt0 = qs - WINDOW; if (kt0 < 0) kt0 = 0;

    for (int kt = kt0; kt <= qs; kt += 64) {
        // ---- load K/V hi/lo tiles (64 x 64 bf16 each) ----
#pragma unroll
        for (int i = 0; i < 16; i++) {
            int idx = tid + i * 128;               // 0..2047
            int buf = idx >> 9;                    // 0 KH,1 KL,2 VH,3 VL
            int rem = idx & 511;
            int r = rem >> 3, c = rem & 7;
            const __nv_bfloat16* base = ((buf & 1) == 0) ? qh : ql;
            int coff = (buf < 2) ? NEMBD : 2 * NEMBD;
            const __nv_bfloat16* src = base
                + ((size_t)(b * SEQ + kt + r)) * RS + coff + hcol + c * 8;
            uint32_t dst = (buf == 0 ? A_KH : buf == 1 ? A_KL : buf == 2 ? A_VH : A_VL);
            *(uint4*)(sm + dst + swz(r, c * 16)) = *(const uint4*)src;
        }
        __syncthreads();

        // ---- S = Q K^T (3-pass split) ----
        float s[8][4];
#pragma unroll
        for (int i = 0; i < 8; i++)
#pragma unroll
            for (int r = 0; r < 4; r++) s[i][r] = 0.f;
#pragma unroll
        for (int kk = 0; kk < 4; kk++) {
            const int cb = kk * 32 + chi;
            uint32_t Kfh[4][4], Kfl[4][4];
#pragma unroll
            for (int bt = 0; bt < 4; bt++) {
                ldsm4(Kfh[bt], sb + A_KH + swz(bt * 16 + l15, cb));
                ldsm4(Kfl[bt], sb + A_KL + swz(bt * 16 + l15, cb));
            }
#pragma unroll
            for (int nt = 0; nt < 8; nt++) {
                uint32_t bh[2] = { Kfh[nt >> 1][nt & 1], Kfh[nt >> 1][(nt & 1) + 2] };
                uint32_t bl[2] = { Kfl[nt >> 1][nt & 1], Kfl[nt >> 1][(nt & 1) + 2] };
                mma16816(s[nt], Qfh[kk], bh);
                mma16816(s[nt], Qfh[kk], bl);
                mma16816(s[nt], Qfl[kk], bh);
            }
        }

        // ---- mask + online softmax ----
        float mx0 = -1e30f, mx1 = -1e30f;
#pragma unroll
        for (int nt = 0; nt < 8; nt++) {
            int j0 = kt + nt * 8 + tig * 2, j1 = j0 + 1;
            float v;
            v = fminf(fmaxf(s[nt][0] * ATT_SCALE, -10000.f), 10000.f);
            v = (j0 <= row0 && j0 > row0 - WINDOW) ? v : -1e30f;
            s[nt][0] = v; mx0 = fmaxf(mx0, v);
            v = fminf(fmaxf(s[nt][1] * ATT_SCALE, -10000.f), 10000.f);
            v = (j1 <= row0 && j1 > row0 - WINDOW) ? v : -1e30f;
            s[nt][1] = v; mx0 = fmaxf(mx0, v);
            v = fminf(fmaxf(s[nt][2] * ATT_SCALE, -10000.f), 10000.f);
            v = (j0 <= row1 && j0 > row1 - WINDOW) ? v : -1e30f;
            s[nt][2] = v; mx1 = fmaxf(mx1, v);
            v = fminf(fmaxf(s[nt][3] * ATT_SCALE, -10000.f), 10000.f);
            v = (j1 <= row1 && j1 > row1 - WINDOW) ? v : -1e30f;
            s[nt][3] = v; mx1 = fmaxf(mx1, v);
        }
        mx0 = qmax(mx0); mx1 = qmax(mx1);
        const float m0n = fmaxf(m0, mx0), m1n = fmaxf(m1, mx1);
        const float c0 = __expf(m0 - m0n), c1 = __expf(m1 - m1n);

        uint32_t ph01[8], ph23[8], pl01[8], pl23[8];
        float sum0 = 0.f, sum1 = 0.f;
#pragma unroll
        for (int nt = 0; nt < 8; nt++) {
            float p0 = __expf(s[nt][0] - m0n), p1 = __expf(s[nt][1] - m0n);
            float p2 = __expf(s[nt][2] - m1n), p3 = __expf(s[nt][3] - m1n);
            sum0 += p0 + p1; sum1 += p2 + p3;
            split2(p0, p1, ph01[nt], pl01[nt]);
            split2(p2, p3, ph23[nt], pl23[nt]);
        }
        sum0 = qsum(sum0); sum1 = qsum(sum1);
        l0 = l0 * c0 + sum0; l1 = l1 * c1 + sum1;
        m0 = m0n; m1 = m1n;
#pragma unroll
        for (int i = 0; i < 8; i++) {
            o[i][0] *= c0; o[i][1] *= c0; o[i][2] *= c1; o[i][3] *= c1;
        }

        // ---- O += P V (3-pass split), V frags via ldmatrix.trans ----
#pragma unroll
        for (int kk = 0; kk < 4; kk++) {
            uint32_t ah[4] = { ph01[2 * kk], ph23[2 * kk], ph01[2 * kk + 1], ph23[2 * kk + 1] };
            uint32_t al[4] = { pl01[2 * kk], pl23[2 * kk], pl01[2 * kk + 1], pl23[2 * kk + 1] };
            uint32_t Vfh[4][4], Vfl[4][4];
#pragma unroll
            for (int db = 0; db < 4; db++) {
                ldsm4t(Vfh[db], sb + A_VH + swz(kk * 16 + l15, db * 32 + chi));
                ldsm4t(Vfl[db], sb + A_VL + swz(kk * 16 + l15, db * 32 + chi));
            }
#pragma unroll
            for (int dnt = 0; dnt < 8; dnt++) {
                uint32_t bh[2] = { Vfh[dnt >> 1][(dnt & 1) * 2], Vfh[dnt >> 1][(dnt & 1) * 2 + 1] };
                uint32_t bl[2] = { Vfl[dnt >> 1][(dnt & 1) * 2], Vfl[dnt >> 1][(dnt & 1) * 2 + 1] };
                mma16816(o[dnt], ah, bh);
                mma16816(o[dnt], ah, bl);
                mma16816(o[dnt], al, bh);
            }
        }
        __syncthreads();
    }

    // ---- epilogue: normalize, split, store ----
    const float i0 = 1.f / l0, i1 = 1.f / l1;
    const size_t tok0 = (size_t)(b * SEQ) + row0;
#pragma unroll
    for (int dnt = 0; dnt < 8; dnt++) {
        int col = hcol + dnt * 8 + tig * 2;
        uint32_t hv, lv;
        split2(o[dnt][0] * i0, o[dnt][1] * i0, hv, lv);
        *(uint32_t*)(oh + tok0 * NEMBD + col) = hv;
        *(uint32_t*)(ol + tok0 * NEMBD + col) = lv;
        split2(o[dnt][2] * i1, o[dnt][3] * i1, hv, lv);
        *(uint32_t*)(oh + (tok0 + 8) * NEMBD + col) = hv;
        *(uint32_t*)(ol + (tok0 + 8) * NEMBD + col) = lv;
    }
}

// ---------------------------------------------------------------------------
extern "C" void kernel_launch(void* const* d_in, const int* in_sizes, int n_in,
                              void* d_out, int out_size) {
    const float* hidden = (const float*)d_in[0];
    const float* w_attn = (const float*)d_in[1];
    const float* b_attn = (const float*)d_in[2];
    const float* w_proj = (const float*)d_in[3];
    const float* b_proj = (const float*)d_in[4];
    float* out = (float*)d_out;

    __nv_bfloat16 *kvh, *kvl, *ah, *al, *wh, *wl, *ph, *pl, *oh, *ol;
    cudaGetSymbolAddress((void**)&kvh, g_kvh); cudaGetSymbolAddress((void**)&kvl, g_kvl);
    cudaGetSymbolAddress((void**)&ah, g_ah); cudaGetSymbolAddress((void**)&al, g_al);
    cudaGetSymbolAddress((void**)&wh, g_wh); cudaGetSymbolAddress((void**)&wl, g_wl);
    cudaGetSymbolAddress((void**)&ph, g_ph); cudaGetSymbolAddress((void**)&pl, g_pl);
    cudaGetSymbolAddress((void**)&oh, g_oh); cudaGetSymbolAddress((void**)&ol, g_ol);

    const int M = BATCH * SEQ;       // 4096
    const int E = NEMBD;             // 1024

    cudaFuncSetAttribute(gemm_bf16_kernel,
                         cudaFuncAttributeMaxDynamicSharedMemorySize, GSMEM);
    cudaFuncSetAttribute(attn_mma_kernel,
                         cudaFuncAttributeMaxDynamicSharedMemorySize, A_SMEM);

    // 0) splits
    {
        int n4 = M * E / 4;
        split_kernel<<<(n4 + 255) / 256, 256>>>(hidden, ah, al, n4);
    }
    split_tr_kernel<<<dim3(3 * E / 32, E / 32), dim3(32, 8)>>>(w_attn, wh, wl, E, 3 * E);
    split_tr_kernel<<<dim3(E / 32, E / 32), dim3(32, 8)>>>(w_proj, ph, pl, E, E);

    // 1) QKV projection -> split bf16 qkv
    gemm_bf16_kernel<<<dim3(3 * E / 128, M / 128), 256, GSMEM>>>(
        ah, al, wh, wl, b_attn, nullptr, kvh, kvl, M, 3 * E, E);
    // 2) flash attention (tensor cores) -> split bf16
    attn_mma_kernel<<<dim3(SEQ / 64, NHEAD, BATCH), 128, A_SMEM>>>(kvh, kvl, oh, ol);
    // 3) output projection -> fp32
    gemm_bf16_kernel<<<dim3(E / 128, M / 128), 256, GSMEM>>>(
        oh, ol, ph, pl, b_proj, out, nullptr, nullptr, M, E, E);
}